// round 12
// baseline (speedup 1.0000x reference)
#include <cuda_runtime.h>

#define BB 8
#define LL 512
#define DD 128
#define INV_SCALE 0.08838834764831843f   // 1/sqrt(128)

typedef unsigned long long ull;

// ---- scratch (no cudaMalloc allowed) ----
__device__ float g_EQ[BB*LL*DD];   // exp(2*Qproj)
__device__ float g_EK[BB*LL*DD];   // exp(2*Kproj)
__device__ float g_V [BB*LL*DD];

__device__ __forceinline__ float frcp(float x) {
    float y;
    asm("rcp.approx.f32 %0, %1;" : "=f"(y) : "f"(x));
    return y;
}
__device__ __forceinline__ ull ffma2(ull a, ull b, ull c) {
    ull d;
    asm("fma.rn.f32x2 %0, %1, %2, %3;" : "=l"(d) : "l"(a), "l"(b), "l"(c));
    return d;
}
__device__ __forceinline__ ull fmul2(ull a, ull b) {
    ull d;
    asm("mul.rn.f32x2 %0, %1, %2;" : "=l"(d) : "l"(a), "l"(b));
    return d;
}
__device__ __forceinline__ ull fadd2(ull a, ull b) {
    ull d;
    asm("add.rn.f32x2 %0, %1, %2;" : "=l"(d) : "l"(a), "l"(b));
    return d;
}
__device__ __forceinline__ ull pack2(float x) {
    ull d;
    asm("mov.b64 %0, {%1, %1};" : "=l"(d) : "f"(x));
    return d;
}
__device__ __forceinline__ ull pack2two(float x, float y) {
    ull d;
    asm("mov.b64 %0, {%1, %2};" : "=l"(d) : "f"(x), "f"(y));
    return d;
}
__device__ __forceinline__ float2 unpack2(ull v) {
    float2 r;
    asm("mov.b64 {%0, %1}, %2;" : "=f"(r.x), "=f"(r.y) : "l"(v));
    return r;
}

// =====================================================================
// Projection: out = f(X @ W.T + b); f = exp(2x) for Q,K, identity for V.
// 128-row x 64-col tiles -> 192 blocks (3 mats x 32 row x 2 col halves),
// 256 threads, thread tile 4x8.  smem: Xs[128][129] + Wt[128][66].
// =====================================================================
#define XS_PITCH 129
#define WT_PITCH 66
#define PROJ_SMEM_FLOATS (128*XS_PITCH + 128*WT_PITCH)   // 24960

__global__ void __launch_bounds__(256) proj_kernel(
    const float* __restrict__ Xq, const float* __restrict__ Xk, const float* __restrict__ Xv,
    const float* __restrict__ Wq, const float* __restrict__ bq,
    const float* __restrict__ Wk, const float* __restrict__ bk,
    const float* __restrict__ Wv, const float* __restrict__ bv)
{
    extern __shared__ float sm[];
    float* Xs = sm;                    // [128][129]
    float* Wt = sm + 128*XS_PITCH;     // [128][66]  Wt[d][c-local]
    __shared__ float bs[64];

    int bx  = blockIdx.x;
    int mat = bx >> 6;                 // 0..2
    int ch  = (bx >> 5) & 1;           // column half
    int rt  = bx & 31;                 // 128-row tile
    const float *X, *W, *bias;
    float* out;
    if (mat == 0)      { X = Xq; W = Wq; bias = bq; out = g_EQ; }
    else if (mat == 1) { X = Xk; W = Wk; bias = bk; out = g_EK; }
    else               { X = Xv; W = Wv; bias = bv; out = g_V;  }

    int tid = threadIdx.x;
    const float4* Xg = (const float4*)(X + rt*128*DD);
    const float4* Wg = (const float4*)W;
    #pragma unroll
    for (int it = 0; it < 16; ++it) {          // X: 128 rows
        int idx = it*256 + tid;                // 0..4095 float4 groups
        int d4  = idx & 31;
        int r   = idx >> 5;
        float4 xv = Xg[idx];
        float* xd = Xs + r*XS_PITCH + 4*d4;
        xd[0] = xv.x; xd[1] = xv.y; xd[2] = xv.z; xd[3] = xv.w;
    }
    #pragma unroll
    for (int it = 0; it < 8; ++it) {           // W: 64 out-rows (this half)
        int idx = it*256 + tid;                // 0..2047
        int d4  = idx & 31;
        int r   = idx >> 5;                    // 0..63
        float4 wv = Wg[(ch*64 + r)*32 + d4];
        Wt[(4*d4+0)*WT_PITCH + r] = wv.x;
        Wt[(4*d4+1)*WT_PITCH + r] = wv.y;
        Wt[(4*d4+2)*WT_PITCH + r] = wv.z;
        Wt[(4*d4+3)*WT_PITCH + r] = wv.w;
    }
    if (tid < 64) bs[tid] = bias[ch*64 + tid];
    __syncthreads();

    int tr = tid >> 3;     // 0..31 (4-row group)
    int tc = tid & 7;      // 0..7  (8-col group)
    const float* xb = Xs + (tr*4)*XS_PITCH;
    const float* wb = Wt + tc*8;

    ull acc[4][4];
    #pragma unroll
    for (int i = 0; i < 4; ++i)
        #pragma unroll
        for (int j = 0; j < 4; ++j) acc[i][j] = 0ull;

    #pragma unroll 4
    for (int d = 0; d < DD; ++d) {
        float xs[4]; ull xp[4]; ull wp[4];
        #pragma unroll
        for (int i = 0; i < 4; ++i) xs[i] = xb[i*XS_PITCH + d];
        #pragma unroll
        for (int j = 0; j < 4; ++j) wp[j] = *(const ull*)(wb + d*WT_PITCH + 2*j);
        #pragma unroll
        for (int i = 0; i < 4; ++i) xp[i] = pack2(xs[i]);
        #pragma unroll
        for (int i = 0; i < 4; ++i)
            #pragma unroll
            for (int j = 0; j < 4; ++j) acc[i][j] = ffma2(xp[i], wp[j], acc[i][j]);
    }

    int rbase = rt*128 + tr*4;
    #pragma unroll
    for (int i = 0; i < 4; ++i) {
        float* orow = out + (rbase + i)*DD + ch*64 + tc*8;
        #pragma unroll
        for (int j = 0; j < 4; ++j) {
            float2 v = unpack2(acc[i][j]);
            float o0 = v.x + bs[tc*8 + 2*j+0];
            float o1 = v.y + bs[tc*8 + 2*j+1];
            if (mat != 2) { o0 = __expf(2.0f*o0); o1 = __expf(2.0f*o1); }
            orow[2*j+0] = o0;
            orow[2*j+1] = o1;
        }
    }
}

// =====================================================================
// Attention. Block = (batch b, 32-q tile), 1024 threads (32 warps).
// Phase 1: tanh(q+k) via exp identity, w and -2 FOLDED INTO TABLES:
//   iw_d = 1/(-2 w_d);  Eq''_d = Eq_d * iw_d
//   D''_d = ffma2(Eq''_d, Ek_d, iw_d) = (1+Eq*Ek)/(-2w)
//   score(shifted) = sum_d 1/D''_d  computed per d-quad:
//     N = (D0+D1)*P23 + (D2+D3)*P01,  Dp = P01*P23,  acc += N*rcp(Dp)
//   12 f32x2 + 2 rcp per 8 elements.  lane = q, warp = k-pair,
//   8 double-buffered 64-k tiles with software-pipelined staging.
// Phase 2: warp-per-row softmax.
// Phase 3: O = P @ V, FFMA2, double-buffered V tiles.
// smem (floats):
//   S[32][516]       @0      16512
//   EKbuf0 (a+b)     @16512   8448   (EKa[32][33]ull2 + EKb)  / V buf0
//   EKbuf1 (a+b)     @24960   8448                            / V buf1
//   EQDa[32][33]ull2 @33408   4224   (dup Eq''_d0, dup Eq''_d1)[d4][q]
//   EQDb[32][33]ull2 @37632   4224
//   IWa[32] ull2     @41856    128   (dup iw0, dup iw1)
//   IWb[32] ull2     @41984    128
//   iw[128]          @42112    128
//   rinv[32]         @42240     32
// =====================================================================
#define S_PITCH 516
#define SM_S     0
#define SM_EK0   16512
#define SM_EK1   24960
#define SM_EQDA  33408
#define SM_EQDB  37632
#define SM_IWA   41856
#define SM_IWB   41984
#define SM_IWS   42112
#define SM_RINV  42240
#define ATTN_SMEM_FLOATS 42272    // 169088 B

__global__ void __launch_bounds__(1024) attn_kernel(
    const float* __restrict__ wdel, const float* __restrict__ wsig,
    const float* __restrict__ wthe, float* __restrict__ out)
{
    extern __shared__ float sm[];
    float*      S    = sm + SM_S;
    ulonglong2* EQDa = (ulonglong2*)(sm + SM_EQDA);   // [d4][33-pitch] by q
    ulonglong2* EQDb = (ulonglong2*)(sm + SM_EQDB);
    ulonglong2* IWa  = (ulonglong2*)(sm + SM_IWA);
    ulonglong2* IWb  = (ulonglong2*)(sm + SM_IWB);
    float*      iw   = sm + SM_IWS;
    float*      rinv = sm + SM_RINV;

    int tid  = threadIdx.x;
    int w    = tid >> 5;
    int lane = tid & 31;
    int b    = blockIdx.x >> 4;
    int qt   = blockIdx.x & 15;
    int qbase = qt * 32;

    const float* EQg = g_EQ + (b*LL + qbase)*DD;
    const float* EKg = g_EK + b*LL*DD;
    const float* Vg  = g_V  + b*LL*DD;

    // ---- init: iw = 1/(-2*w_all) ----
    if (tid < DD) {
        float wv = INV_SCALE + wdel[tid] + wsig[tid] + wthe[tid];
        iw[tid] = 1.0f / (-2.0f * wv);
    }
    __syncthreads();

    // ---- init tables + prologue EK stage (tile 0) ----
    {   // EQD: cell (q = tid>>5, d4 = lane)
        int q  = tid >> 5;
        int d4 = tid & 31;
        float4 e = ((const float4*)EQg)[q*32 + d4];
        float i0 = iw[4*d4+0], i1 = iw[4*d4+1], i2 = iw[4*d4+2], i3 = iw[4*d4+3];
        ulonglong2 ua; ua.x = pack2(e.x*i0); ua.y = pack2(e.y*i1);
        ulonglong2 ub; ub.x = pack2(e.z*i2); ub.y = pack2(e.w*i3);
        EQDa[d4*33 + q] = ua;
        EQDb[d4*33 + q] = ub;
    }
    if (tid < 32) {
        ulonglong2 ua; ua.x = pack2(iw[4*tid+0]); ua.y = pack2(iw[4*tid+1]);
        ulonglong2 ub; ub.x = pack2(iw[4*tid+2]); ub.y = pack2(iw[4*tid+3]);
        IWa[tid] = ua; IWb[tid] = ub;
    }
    int sj  = tid >> 5;     // staging: j = warp id
    int sd4 = tid & 31;
    const float4* EK4g = (const float4*)EKg;
    {   // stage tile 0 into buf 0
        float4 La = EK4g[(2*sj  )*32 + sd4];
        float4 Lb = EK4g[(2*sj+1)*32 + sd4];
        ulonglong2* EKa0 = (ulonglong2*)(sm + SM_EK0);
        ulonglong2* EKb0 = EKa0 + 1056;
        ulonglong2 ua; ua.x = pack2two(La.x, Lb.x); ua.y = pack2two(La.y, Lb.y);
        ulonglong2 ub; ub.x = pack2two(La.z, Lb.z); ub.y = pack2two(La.w, Lb.w);
        EKa0[sj*33 + sd4] = ua;
        EKb0[sj*33 + sd4] = ub;
    }
    __syncthreads();

    // ---------------- Phase 1: scores (pipelined over 8 x 64-k tiles) ----------------
    for (int kt = 0; kt < 8; ++kt) {
        int cur = kt & 1;
        float4 La, Lb;
        if (kt < 7) {   // issue next tile's global loads early
            La = EK4g[((kt+1)*64 + 2*sj  )*32 + sd4];
            Lb = EK4g[((kt+1)*64 + 2*sj+1)*32 + sd4];
        }

        const ulonglong2* EKa = (const ulonglong2*)(sm + SM_EK0 + cur*8448);
        const ulonglong2* EKb = EKa + 1056;
        ull acc = 0ull;
        #pragma unroll 4
        for (int d4 = 0; d4 < 32; ++d4) {
            ulonglong2 ea = EQDa[d4*33 + lane];
            ulonglong2 eb = EQDb[d4*33 + lane];
            ulonglong2 ia = IWa[d4];
            ulonglong2 ib = IWb[d4];
            ulonglong2 ka = EKa[w*33 + d4];
            ulonglong2 kb = EKb[w*33 + d4];
            ull D0 = ffma2(ea.x, ka.x, ia.x);
            ull D1 = ffma2(ea.y, ka.y, ia.y);
            ull D2 = ffma2(eb.x, kb.x, ib.x);
            ull D3 = ffma2(eb.y, kb.y, ib.y);
            ull n01 = fadd2(D0, D1);
            ull n23 = fadd2(D2, D3);
            ull P01 = fmul2(D0, D1);
            ull P23 = fmul2(D2, D3);
            ull N   = ffma2(n23, P01, fmul2(n01, P23));
            ull Dp  = fmul2(P01, P23);
            float2 df = unpack2(Dp);
            ull R = pack2two(frcp(df.x), frcp(df.y));
            acc = ffma2(N, R, acc);
        }
        *(float2*)(S + lane*S_PITCH + kt*64 + 2*w) = unpack2(acc);

        if (kt < 7) {   // store next tile into the other buffer
            ulonglong2* EKan = (ulonglong2*)(sm + SM_EK0 + (cur^1)*8448);
            ulonglong2* EKbn = EKan + 1056;
            ulonglong2 ua; ua.x = pack2two(La.x, Lb.x); ua.y = pack2two(La.y, Lb.y);
            ulonglong2 ub; ub.x = pack2two(La.z, Lb.z); ub.y = pack2two(La.w, Lb.w);
            EKan[sj*33 + sd4] = ua;
            EKbn[sj*33 + sd4] = ub;
        }
        __syncthreads();
    }

    // ---------------- Phase 2: softmax (constants dropped are invariant) ----------------
    {
        float* Srow = S + w*S_PITCH;
        float v[16];
        float m = -1e30f;
        #pragma unroll
        for (int i = 0; i < 16; ++i) { v[i] = Srow[i*32 + lane]; m = fmaxf(m, v[i]); }
        #pragma unroll
        for (int s = 16; s > 0; s >>= 1) m = fmaxf(m, __shfl_xor_sync(0xffffffffu, m, s));
        float sum = 0.f;
        #pragma unroll
        for (int i = 0; i < 16; ++i) {
            float e = __expf(v[i] - m);
            Srow[i*32 + lane] = e;
            sum += e;
        }
        #pragma unroll
        for (int s = 16; s > 0; s >>= 1) sum += __shfl_xor_sync(0xffffffffu, sum, s);
        if (lane == 0) rinv[w] = 1.0f / sum;
    }

    // ---- phase 3 prologue: stage V tile 0 into buf 0 (overlaps softmax) ----
    const float4* V4g = (const float4*)Vg;
    {
        float4 Va = V4g[(2*sj  )*32 + sd4];
        float4 Vb = V4g[(2*sj+1)*32 + sd4];
        float2* Vp2 = (float2*)(sm + SM_EK0);
        Vp2[sj*128 + 4*sd4 + 0] = make_float2(Va.x, Vb.x);
        Vp2[sj*128 + 4*sd4 + 1] = make_float2(Va.y, Vb.y);
        Vp2[sj*128 + 4*sd4 + 2] = make_float2(Va.z, Vb.z);
        Vp2[sj*128 + 4*sd4 + 3] = make_float2(Va.w, Vb.w);
    }
    __syncthreads();

    // ---------------- Phase 3: O = P @ V (pipelined, FFMA2) ----------------
    int r0  = (w & 15) * 2;
    int dh  = w >> 4;
    int dA  = dh*64 + lane;
    ull acc3[2][2] = {{0,0},{0,0}};

    for (int kt = 0; kt < 8; ++kt) {
        int cur = kt & 1;
        float4 Va, Vb;
        if (kt < 7) {
            Va = V4g[((kt+1)*64 + 2*sj  )*32 + sd4];
            Vb = V4g[((kt+1)*64 + 2*sj+1)*32 + sd4];
        }

        const ull* Vp = (const ull*)(sm + SM_EK0 + cur*8448);   // [32][128]
        const float* Sb = S + kt*64;
        #pragma unroll 4
        for (int k2 = 0; k2 < 32; ++k2) {
            ull p0 = *(const ull*)(Sb + (r0+0)*S_PITCH + 2*k2);
            ull p1 = *(const ull*)(Sb + (r0+1)*S_PITCH + 2*k2);
            ull v0 = Vp[k2*128 + dA];
            ull v1 = Vp[k2*128 + dA + 32];
            acc3[0][0] = ffma2(p0, v0, acc3[0][0]);  acc3[0][1] = ffma2(p0, v1, acc3[0][1]);
            acc3[1][0] = ffma2(p1, v0, acc3[1][0]);  acc3[1][1] = ffma2(p1, v1, acc3[1][1]);
        }

        if (kt < 7) {
            float2* Vp2n = (float2*)(sm + SM_EK0 + (cur^1)*8448);
            Vp2n[sj*128 + 4*sd4 + 0] = make_float2(Va.x, Vb.x);
            Vp2n[sj*128 + 4*sd4 + 1] = make_float2(Va.y, Vb.y);
            Vp2n[sj*128 + 4*sd4 + 2] = make_float2(Va.z, Vb.z);
            Vp2n[sj*128 + 4*sd4 + 3] = make_float2(Va.w, Vb.w);
        }
        __syncthreads();
    }

    #pragma unroll
    for (int i = 0; i < 2; ++i) {
        float inv = rinv[r0 + i];
        float2 eo = unpack2(acc3[i][0]);
        float2 e1 = unpack2(acc3[i][1]);
        float* orow = out + (size_t)(b*LL + qbase + r0 + i)*DD;
        orow[dA]      = (eo.x + eo.y) * inv;
        orow[dA + 32] = (e1.x + e1.y) * inv;
    }
}

// =====================================================================
extern "C" void kernel_launch(void* const* d_in, const int* in_sizes, int n_in,
                              void* d_out, int out_size)
{
    const float* query = (const float*)d_in[0];
    const float* key   = (const float*)d_in[1];
    const float* value = (const float*)d_in[2];
    const float* Wq    = (const float*)d_in[3];
    const float* bq    = (const float*)d_in[4];
    const float* Wk    = (const float*)d_in[5];
    const float* bk    = (const float*)d_in[6];
    const float* Wv    = (const float*)d_in[7];
    const float* bv    = (const float*)d_in[8];
    const float* wdel  = (const float*)d_in[9];
    const float* wsig  = (const float*)d_in[11];
    const float* wthe  = (const float*)d_in[13];
    float* out = (float*)d_out;

    const int PROJ_SMEM = PROJ_SMEM_FLOATS * (int)sizeof(float);   // 99840
    const int ATTN_SMEM = ATTN_SMEM_FLOATS * (int)sizeof(float);   // 169088

    cudaFuncSetAttribute(proj_kernel, cudaFuncAttributeMaxDynamicSharedMemorySize, PROJ_SMEM);
    cudaFuncSetAttribute(attn_kernel, cudaFuncAttributeMaxDynamicSharedMemorySize, ATTN_SMEM);

    proj_kernel<<<192, 256, PROJ_SMEM>>>(query, key, value, Wq, bq, Wk, bk, Wv, bv);
    attn_kernel<<<BB*16, 1024, ATTN_SMEM>>>(wdel, wsig, wthe, out);
}

// round 13
// speedup vs baseline: 1.2063x; 1.2063x over previous
#include <cuda_runtime.h>

#define BB 8
#define LL 512
#define DD 128
#define INV_SCALE 0.08838834764831843f   // 1/sqrt(128)

typedef unsigned long long ull;

// ---- scratch (no cudaMalloc allowed) ----
__device__ float g_EQ[BB*LL*DD];   // exp(2*Qproj)
__device__ float g_EK[BB*LL*DD];   // exp(2*Kproj)
__device__ float g_V [BB*LL*DD];

__device__ __forceinline__ float frcp(float x) {
    float y;
    asm("rcp.approx.f32 %0, %1;" : "=f"(y) : "f"(x));
    return y;
}
__device__ __forceinline__ ull ffma2(ull a, ull b, ull c) {
    ull d;
    asm("fma.rn.f32x2 %0, %1, %2, %3;" : "=l"(d) : "l"(a), "l"(b), "l"(c));
    return d;
}
__device__ __forceinline__ ull fmul2(ull a, ull b) {
    ull d;
    asm("mul.rn.f32x2 %0, %1, %2;" : "=l"(d) : "l"(a), "l"(b));
    return d;
}
__device__ __forceinline__ ull fadd2(ull a, ull b) {
    ull d;
    asm("add.rn.f32x2 %0, %1, %2;" : "=l"(d) : "l"(a), "l"(b));
    return d;
}
__device__ __forceinline__ ull pack2(float x) {
    ull d;
    asm("mov.b64 %0, {%1, %1};" : "=l"(d) : "f"(x));
    return d;
}
__device__ __forceinline__ ull pack2two(float x, float y) {
    ull d;
    asm("mov.b64 %0, {%1, %2};" : "=l"(d) : "f"(x), "f"(y));
    return d;
}
__device__ __forceinline__ float2 unpack2(ull v) {
    float2 r;
    asm("mov.b64 {%0, %1}, %2;" : "=f"(r.x), "=f"(r.y) : "l"(v));
    return r;
}

// =====================================================================
// Projection (measured-best config: 96 blocks, 128x128 tiles, 256 thr,
// 8x8 thread tile, FFMA2).  Epilogue: exp(2x) for Q,K; identity for V.
// smem: Xs[128][129] + Wt[128][130] = 132608 B
// =====================================================================
#define XS_PITCH 129
#define WT_PITCH 130
#define PROJ_SMEM_FLOATS (128*XS_PITCH + 128*WT_PITCH)

__global__ void __launch_bounds__(256) proj_kernel(
    const float* __restrict__ Xq, const float* __restrict__ Xk, const float* __restrict__ Xv,
    const float* __restrict__ Wq, const float* __restrict__ bq,
    const float* __restrict__ Wk, const float* __restrict__ bk,
    const float* __restrict__ Wv, const float* __restrict__ bv)
{
    extern __shared__ float sm[];
    float* Xs = sm;                    // [128][129]
    float* Wt = sm + 128*XS_PITCH;     // [128][130]  Wt[d][c]
    __shared__ float bs[DD];

    int bx  = blockIdx.x;
    int mat = bx >> 5;
    int rt  = bx & 31;
    const float *X, *W, *bias;
    float* out;
    if (mat == 0)      { X = Xq; W = Wq; bias = bq; out = g_EQ; }
    else if (mat == 1) { X = Xk; W = Wk; bias = bk; out = g_EK; }
    else               { X = Xv; W = Wv; bias = bv; out = g_V;  }

    int tid = threadIdx.x;
    const float4* Xg = (const float4*)(X + rt*128*DD);
    const float4* Wg = (const float4*)W;
    #pragma unroll
    for (int it = 0; it < 16; ++it) {
        int idx = it*256 + tid;           // 0..4095 float4 groups
        int d4  = idx & 31;
        int r   = idx >> 5;
        float4 xv = Xg[idx];
        float* xd = Xs + r*XS_PITCH + 4*d4;
        xd[0] = xv.x; xd[1] = xv.y; xd[2] = xv.z; xd[3] = xv.w;
        float4 wv = Wg[idx];
        Wt[(4*d4+0)*WT_PITCH + r] = wv.x;
        Wt[(4*d4+1)*WT_PITCH + r] = wv.y;
        Wt[(4*d4+2)*WT_PITCH + r] = wv.z;
        Wt[(4*d4+3)*WT_PITCH + r] = wv.w;
    }
    if (tid < DD) bs[tid] = bias[tid];
    __syncthreads();

    int tr = tid >> 4;     // 0..15 (8-row group)
    int tc = tid & 15;     // 0..15 (8-col group)
    const float* xb = Xs + (tr*8)*XS_PITCH;
    const float* wb = Wt + tc*8;

    ull acc[8][4];
    #pragma unroll
    for (int i = 0; i < 8; ++i)
        #pragma unroll
        for (int j = 0; j < 4; ++j) acc[i][j] = 0ull;

    #pragma unroll 4
    for (int d = 0; d < DD; ++d) {
        float xs[8]; ull xp[8]; ull wp[4];
        #pragma unroll
        for (int i = 0; i < 8; ++i) xs[i] = xb[i*XS_PITCH + d];
        #pragma unroll
        for (int j = 0; j < 4; ++j) wp[j] = *(const ull*)(wb + d*WT_PITCH + 2*j);
        #pragma unroll
        for (int i = 0; i < 8; ++i) xp[i] = pack2(xs[i]);
        #pragma unroll
        for (int i = 0; i < 8; ++i)
            #pragma unroll
            for (int j = 0; j < 4; ++j) acc[i][j] = ffma2(xp[i], wp[j], acc[i][j]);
    }

    int rbase = rt*128 + tr*8;
    #pragma unroll
    for (int i = 0; i < 8; ++i) {
        float* orow = out + (rbase + i)*DD + tc*8;
        #pragma unroll
        for (int j = 0; j < 4; ++j) {
            float2 v = unpack2(acc[i][j]);
            float o0 = v.x + bs[tc*8 + 2*j+0];
            float o1 = v.y + bs[tc*8 + 2*j+1];
            if (mat != 2) { o0 = __expf(2.0f*o0); o1 = __expf(2.0f*o1); }
            orow[2*j+0] = o0;
            orow[2*j+1] = o1;
        }
    }
}

// =====================================================================
// Attention (R11 layout + iw-folded 12-op inner loop).
// Block = (batch b, 32-q tile), 1024 threads (32 warps), lane = q.
// Phase 1: iw_d = 1/(-2 w_d), Eq''_d = Eq_d*iw_d (in EQ4 table).
//   D_d = ffma2(dup(Eq''_d), ekpair_d, dup(iw_d)) = (1+Eq*Ek)/(-2w)
//   score(shifted) = sum_d 1/D_d; per d-quad:
//     N=(D0+D1)*P23+(D2+D3)*P01, Dp=P01*P23, acc += N*rcp(Dp)
//   Warp w owns k-pairs (2w, 2w+1) of each 128-k tile (4 tiles).
// Phase 2: warp-per-row softmax.
// Phase 3: O = P @ V, FFMA2 (R11 scheme).
// smem (floats):
//   S[32][516]          @ 0       16512  (first 128 reused as iw temp)
//   EKa[32][65] ull2    @ 16512    8320  (pairs d0,d1; Vp reuses this)
//   EKb[32][65] ull2    @ 24832    8320  (pairs d2,d3)
//   EQ4[32][32] float4  @ 33152    4096  (EQ4[d4][q] = Eq'' quad, non-dup)
//   IWa[32] ull2        @ 37248     128  (dup iw0, dup iw1)
//   IWb[32] ull2        @ 37376     128
//   rinv[32]            @ 37504
// =====================================================================
#define S_PITCH 516
#define SM_S    0
#define SM_EKA  16512
#define SM_EKB  24832
#define SM_EQ4  33152
#define SM_IWA  37248
#define SM_IWB  37376
#define SM_RINV 37504
#define ATTN_SMEM_FLOATS 37536    // 150144 B

__global__ void __launch_bounds__(1024) attn_kernel(
    const float* __restrict__ wdel, const float* __restrict__ wsig,
    const float* __restrict__ wthe, float* __restrict__ out)
{
    extern __shared__ float sm[];
    float*      S    = sm + SM_S;
    ulonglong2* EKa  = (ulonglong2*)(sm + SM_EKA);   // [32][65]
    ulonglong2* EKb  = (ulonglong2*)(sm + SM_EKB);   // [32][65]
    float4*     EQ4  = (float4*)(sm + SM_EQ4);       // [d4][q]
    ulonglong2* IWa  = (ulonglong2*)(sm + SM_IWA);
    ulonglong2* IWb  = (ulonglong2*)(sm + SM_IWB);
    float*      rinv = sm + SM_RINV;
    float*      iw   = sm + SM_S;                    // temp during init

    int tid  = threadIdx.x;
    int w    = tid >> 5;
    int lane = tid & 31;
    int b    = blockIdx.x >> 4;
    int qt   = blockIdx.x & 15;
    int qbase = qt * 32;

    const float* EQg = g_EQ + (b*LL + qbase)*DD;
    const float* EKg = g_EK + b*LL*DD;
    const float* Vg  = g_V  + b*LL*DD;

    // ---- init: iw = 1/(-2*w_all) ----
    if (tid < DD) {
        float wv = INV_SCALE + wdel[tid] + wsig[tid] + wthe[tid];
        iw[tid] = 1.0f / (-2.0f * wv);
    }
    __syncthreads();

    // ---- tables: EQ4[d4][q] = Eq * iw (folded), IW dup tables ----
    {
        int q  = tid & 31;
        int d4 = tid >> 5;
        float4 e = ((const float4*)EQg)[q*32 + d4];
        e.x *= iw[4*d4+0]; e.y *= iw[4*d4+1];
        e.z *= iw[4*d4+2]; e.w *= iw[4*d4+3];
        EQ4[d4*32 + q] = e;
    }
    if (tid < 32) {
        ulonglong2 ua; ua.x = pack2(iw[4*tid+0]); ua.y = pack2(iw[4*tid+1]);
        ulonglong2 ub; ub.x = pack2(iw[4*tid+2]); ub.y = pack2(iw[4*tid+3]);
        IWa[tid] = ua; IWb[tid] = ub;
    }
    // ordered by first kt-loop __syncthreads (iw temp is only re-used by
    // phase-1 S writes, which come after further barriers)

    // ---------------- Phase 1: scores ----------------
    int j0 = 2*w;                 // this warp's k-pair indices (j0, j0+1)

    for (int kt = 0; kt < 4; ++kt) {          // 4 tiles of 128 k
        __syncthreads();   // EK region free (covers table init on kt=0)
        {   // stage 128-k tile: cells (d4, j), j = k-pair 0..63
            const float4* EK4g = (const float4*)(EKg + kt*128*DD);
            #pragma unroll
            for (int it = 0; it < 2; ++it) {
                int cidx = it*1024 + tid;      // 0..2047
                int d4 = cidx & 31;
                int j  = cidx >> 5;            // 0..63
                float4 a  = EK4g[(2*j)*32 + d4];
                float4 bb = EK4g[(2*j+1)*32 + d4];
                ulonglong2 ua; ua.x = pack2two(a.x, bb.x); ua.y = pack2two(a.y, bb.y);
                ulonglong2 ub; ub.x = pack2two(a.z, bb.z); ub.y = pack2two(a.w, bb.w);
                EKa[d4*65 + j] = ua;
                EKb[d4*65 + j] = ub;
            }
        }
        __syncthreads();

        ull acc0 = 0ull, acc1 = 0ull;
        #pragma unroll 4
        for (int d4 = 0; d4 < 32; ++d4) {
            float4 eqv = EQ4[d4*32 + lane];
            ull eq0 = pack2(eqv.x), eq1 = pack2(eqv.y);
            ull eq2 = pack2(eqv.z), eq3 = pack2(eqv.w);
            ulonglong2 ia = IWa[d4];
            ulonglong2 ib = IWb[d4];
            #pragma unroll
            for (int jj = 0; jj < 2; ++jj) {
                ulonglong2 ka = EKa[d4*65 + j0 + jj];
                ulonglong2 kb = EKb[d4*65 + j0 + jj];
                ull D0 = ffma2(eq0, ka.x, ia.x);
                ull D1 = ffma2(eq1, ka.y, ia.y);
                ull D2 = ffma2(eq2, kb.x, ib.x);
                ull D3 = ffma2(eq3, kb.y, ib.y);
                ull n01 = fadd2(D0, D1);
                ull n23 = fadd2(D2, D3);
                ull P01 = fmul2(D0, D1);
                ull P23 = fmul2(D2, D3);
                ull N   = ffma2(n23, P01, fmul2(n01, P23));
                ull Dp  = fmul2(P01, P23);
                float2 df = unpack2(Dp);
                ull R = pack2two(frcp(df.x), frcp(df.y));
                if (jj == 0) acc0 = ffma2(N, R, acc0);
                else         acc1 = ffma2(N, R, acc1);
            }
        }
        float2 s0 = unpack2(acc0);
        float2 s1 = unpack2(acc1);
        *(float4*)(S + lane*S_PITCH + kt*128 + 4*w) = make_float4(s0.x, s0.y, s1.x, s1.y);
    }
    __syncthreads();   // each row assembled from all 32 warps

    // ---------------- Phase 2: softmax ----------------
    {
        float* Srow = S + w*S_PITCH;
        float v[16];
        float m = -1e30f;
        #pragma unroll
        for (int i = 0; i < 16; ++i) { v[i] = Srow[i*32 + lane]; m = fmaxf(m, v[i]); }
        #pragma unroll
        for (int s = 16; s > 0; s >>= 1) m = fmaxf(m, __shfl_xor_sync(0xffffffffu, m, s));
        float sum = 0.f;
        #pragma unroll
        for (int i = 0; i < 16; ++i) {
            float e = __expf(v[i] - m);
            Srow[i*32 + lane] = e;
            sum += e;
        }
        #pragma unroll
        for (int s = 16; s > 0; s >>= 1) sum += __shfl_xor_sync(0xffffffffu, sum, s);
        if (lane == 0) rinv[w] = 1.0f / sum;
    }

    // ---------------- Phase 3: O = P @ V (FFMA2) ----------------
    int r0  = (w & 15) * 2;
    int dh  = w >> 4;
    int dA  = dh*64 + lane;
    ull acc3[2][2] = {{0,0},{0,0}};
    const ull* Vp = (const ull*)(sm + SM_EKA);   // [32][128] : Vp[k2][d]

    for (int kt = 0; kt < 8; ++kt) {             // 8 tiles of 64 k
        __syncthreads();   // previous tile consumed (kt=0: softmax done)
        {
            const float4* Va = (const float4*)(Vg + kt*64*DD);
            float2* Vp2 = (float2*)(sm + SM_EKA);
            int k2 = tid >> 5, d4 = tid & 31;
            float4 a  = Va[(2*k2)*32 + d4];
            float4 bb = Va[(2*k2+1)*32 + d4];
            Vp2[k2*128 + 4*d4 + 0] = make_float2(a.x, bb.x);
            Vp2[k2*128 + 4*d4 + 1] = make_float2(a.y, bb.y);
            Vp2[k2*128 + 4*d4 + 2] = make_float2(a.z, bb.z);
            Vp2[k2*128 + 4*d4 + 3] = make_float2(a.w, bb.w);
        }
        __syncthreads();

        const float* Sb = S + kt*64;
        #pragma unroll 4
        for (int k2 = 0; k2 < 32; ++k2) {
            ull p0 = *(const ull*)(Sb + (r0+0)*S_PITCH + 2*k2);
            ull p1 = *(const ull*)(Sb + (r0+1)*S_PITCH + 2*k2);
            ull v0 = Vp[k2*128 + dA];
            ull v1 = Vp[k2*128 + dA + 32];
            acc3[0][0] = ffma2(p0, v0, acc3[0][0]);  acc3[0][1] = ffma2(p0, v1, acc3[0][1]);
            acc3[1][0] = ffma2(p1, v0, acc3[1][0]);  acc3[1][1] = ffma2(p1, v1, acc3[1][1]);
        }
    }

    #pragma unroll
    for (int i = 0; i < 2; ++i) {
        float inv = rinv[r0 + i];
        float2 eo = unpack2(acc3[i][0]);
        float2 e1 = unpack2(acc3[i][1]);
        float* orow = out + (size_t)(b*LL + qbase + r0 + i)*DD;
        orow[dA]      = (eo.x + eo.y) * inv;
        orow[dA + 32] = (e1.x + e1.y) * inv;
    }
}

// =====================================================================
extern "C" void kernel_launch(void* const* d_in, const int* in_sizes, int n_in,
                              void* d_out, int out_size)
{
    const float* query = (const float*)d_in[0];
    const float* key   = (const float*)d_in[1];
    const float* value = (const float*)d_in[2];
    const float* Wq    = (const float*)d_in[3];
    const float* bq    = (const float*)d_in[4];
    const float* Wk    = (const float*)d_in[5];
    const float* bk    = (const float*)d_in[6];
    const float* Wv    = (const float*)d_in[7];
    const float* bv    = (const float*)d_in[8];
    const float* wdel  = (const float*)d_in[9];
    const float* wsig  = (const float*)d_in[11];
    const float* wthe  = (const float*)d_in[13];
    float* out = (float*)d_out;

    const int PROJ_SMEM = PROJ_SMEM_FLOATS * (int)sizeof(float);   // 132608
    const int ATTN_SMEM = ATTN_SMEM_FLOATS * (int)sizeof(float);   // 150144

    cudaFuncSetAttribute(proj_kernel, cudaFuncAttributeMaxDynamicSharedMemorySize, PROJ_SMEM);
    cudaFuncSetAttribute(attn_kernel, cudaFuncAttributeMaxDynamicSharedMemorySize, ATTN_SMEM);

    proj_kernel<<<96, 256, PROJ_SMEM>>>(query, key, value, Wq, bq, Wk, bk, Wv, bv);
    attn_kernel<<<BB*16, 1024, ATTN_SMEM>>>(wdel, wsig, wthe, out);
}